// round 1
// baseline (speedup 1.0000x reference)
#include <cuda_runtime.h>

#define FULL_MASK 0xffffffffu

constexpr int THREADS = 512;
constexpr int MT   = 64;    // rows per CTA
constexpr int FDIM = 512;   // output features
constexpr int KDIM = 128;   // input features
constexpr int KB   = 32;    // k-block staged in smem
constexpr float BN_EPS = 1e-3f;

// smem layout (floats): sA[64*32]=2048 | sW[32*512]=16384 | sS[512] | sT[512]
constexpr int SMEM_FLOATS = 2048 + 16384 + 512 + 512;

__global__ __launch_bounds__(THREADS, 1)
void attn_fused_kernel(const float* __restrict__ A,      // [B,128]
                       const float* __restrict__ prior,  // [B,512]
                       const float* __restrict__ W,      // [128,512]
                       const float* __restrict__ bias,   // [512]
                       const float* __restrict__ gamma,  // [512]
                       const float* __restrict__ beta,   // [512]
                       const float* __restrict__ mmean,  // [512]
                       const float* __restrict__ mvar,   // [512]
                       float* __restrict__ out)          // [B,512]
{
    extern __shared__ float sm[];
    float* sA = sm;                    // [64][32]
    float* sW = sm + 2048;             // [32][512]
    float* sS = sm + 2048 + 16384;     // [512] scale
    float* sT = sS + 512;              // [512] shift

    const int tid  = threadIdx.x;
    const int warp = tid >> 5;
    const int lane = tid & 31;
    const int rowbase = blockIdx.x * MT;
    const int r0 = warp * 4;           // warp owns rows r0..r0+3 of the tile

    // BN constants: z_bn = dot * s + t, with bias folded in.
    {
        float s = gamma[tid] * rsqrtf(mvar[tid] + BN_EPS);
        sS[tid] = s;
        sT[tid] = (bias[tid] - mmean[tid]) * s + beta[tid];
    }

    float acc[4][4][4];  // [col-subgroup][row][col-in-float4]
#pragma unroll
    for (int sg = 0; sg < 4; sg++)
#pragma unroll
        for (int r = 0; r < 4; r++)
#pragma unroll
            for (int c = 0; c < 4; c++) acc[sg][r][c] = 0.f;

    // ---- GEMM mainloop: K in blocks of 32 ----
#pragma unroll 1
    for (int kb = 0; kb < KDIM / KB; ++kb) {
        // stage A tile [64][32] (1 float4 per thread, coalesced)
        {
            int r  = tid >> 3;
            int kk = (tid & 7) << 2;
            *(float4*)&sA[r * KB + kk] =
                *(const float4*)&A[(size_t)(rowbase + r) * KDIM + kb * KB + kk];
        }
        // stage W tile [32][512] (8 float4 per thread, coalesced)
#pragma unroll
        for (int p = 0; p < 8; p++) {
            int j  = tid + THREADS * p;
            int k  = j >> 7;
            int c4 = (j & 127) << 2;
            *(float4*)&sW[k * FDIM + c4] =
                *(const float4*)&W[(size_t)(kb * KB + k) * FDIM + c4];
        }
        __syncthreads();

#pragma unroll
        for (int k4 = 0; k4 < KB / 4; ++k4) {
            float4 a0 = *(float4*)&sA[(r0 + 0) * KB + k4 * 4];
            float4 a1 = *(float4*)&sA[(r0 + 1) * KB + k4 * 4];
            float4 a2 = *(float4*)&sA[(r0 + 2) * KB + k4 * 4];
            float4 a3 = *(float4*)&sA[(r0 + 3) * KB + k4 * 4];
            float a_[4][4];
            a_[0][0]=a0.x; a_[0][1]=a0.y; a_[0][2]=a0.z; a_[0][3]=a0.w;
            a_[1][0]=a1.x; a_[1][1]=a1.y; a_[1][2]=a1.z; a_[1][3]=a1.w;
            a_[2][0]=a2.x; a_[2][1]=a2.y; a_[2][2]=a2.z; a_[2][3]=a2.w;
            a_[3][0]=a3.x; a_[3][1]=a3.y; a_[3][2]=a3.z; a_[3][3]=a3.w;
#pragma unroll
            for (int t = 0; t < 4; t++) {
                const int k = k4 * 4 + t;
#pragma unroll
                for (int sg = 0; sg < 4; sg++) {
                    float4 w = *(float4*)&sW[k * FDIM + sg * 128 + lane * 4];
#pragma unroll
                    for (int r = 0; r < 4; r++) {
                        acc[sg][r][0] = fmaf(a_[r][t], w.x, acc[sg][r][0]);
                        acc[sg][r][1] = fmaf(a_[r][t], w.y, acc[sg][r][1]);
                        acc[sg][r][2] = fmaf(a_[r][t], w.z, acc[sg][r][2]);
                        acc[sg][r][3] = fmaf(a_[r][t], w.w, acc[sg][r][3]);
                    }
                }
            }
        }
        __syncthreads();
    }

    // ---- epilogue: BN + prior scale (in place) ----
#pragma unroll
    for (int r = 0; r < 4; r++) {
        const size_t grow = (size_t)(rowbase + r0 + r);
#pragma unroll
        for (int sg = 0; sg < 4; sg++) {
            float4 sv = *(float4*)&sS[sg * 128 + lane * 4];
            float4 tv = *(float4*)&sT[sg * 128 + lane * 4];
            float4 pr = *(const float4*)&prior[grow * FDIM + sg * 128 + lane * 4];
            acc[sg][r][0] = (acc[sg][r][0] * sv.x + tv.x) * pr.x;
            acc[sg][r][1] = (acc[sg][r][1] * sv.y + tv.y) * pr.y;
            acc[sg][r][2] = (acc[sg][r][2] * sv.z + tv.z) * pr.z;
            acc[sg][r][3] = (acc[sg][r][3] * sv.w + tv.w) * pr.w;
        }
    }

    // ---- sparsemax: 4 rows per warp, each row's 512 values live in this warp ----
    // row max
    float mx[4];
#pragma unroll
    for (int r = 0; r < 4; r++) {
        float m = acc[0][r][0];
#pragma unroll
        for (int sg = 0; sg < 4; sg++)
#pragma unroll
            for (int c = 0; c < 4; c++) m = fmaxf(m, acc[sg][r][c]);
        mx[r] = m;
    }
#pragma unroll
    for (int off = 16; off; off >>= 1) {
#pragma unroll
        for (int r = 0; r < 4; r++)
            mx[r] = fmaxf(mx[r], __shfl_xor_sync(FULL_MASK, mx[r], off));
    }

    // bisection on tau in [max-1, max]; f(tau)=sum(relu(z-tau)) is monotone dec.
    float lo[4], hi[4];
#pragma unroll
    for (int r = 0; r < 4; r++) { lo[r] = mx[r] - 1.0f; hi[r] = mx[r]; }

#pragma unroll 1
    for (int it = 0; it < 22; ++it) {
        float mid[4], s4[4];
#pragma unroll
        for (int r = 0; r < 4; r++) { mid[r] = 0.5f * (lo[r] + hi[r]); s4[r] = 0.f; }
#pragma unroll
        for (int sg = 0; sg < 4; sg++)
#pragma unroll
            for (int r = 0; r < 4; r++)
#pragma unroll
                for (int c = 0; c < 4; c++)
                    s4[r] += fmaxf(acc[sg][r][c] - mid[r], 0.f);
#pragma unroll
        for (int off = 16; off; off >>= 1) {
#pragma unroll
            for (int r = 0; r < 4; r++)
                s4[r] += __shfl_xor_sync(FULL_MASK, s4[r], off);
        }
#pragma unroll
        for (int r = 0; r < 4; r++) {
            if (s4[r] >= 1.0f) lo[r] = mid[r]; else hi[r] = mid[r];
        }
    }

    // write out = relu(z - tau)
#pragma unroll
    for (int r = 0; r < 4; r++) {
        const float tau = 0.5f * (lo[r] + hi[r]);
        const size_t grow = (size_t)(rowbase + r0 + r);
#pragma unroll
        for (int sg = 0; sg < 4; sg++) {
            float4 o;
            o.x = fmaxf(acc[sg][r][0] - tau, 0.f);
            o.y = fmaxf(acc[sg][r][1] - tau, 0.f);
            o.z = fmaxf(acc[sg][r][2] - tau, 0.f);
            o.w = fmaxf(acc[sg][r][3] - tau, 0.f);
            *(float4*)&out[grow * FDIM + sg * 128 + lane * 4] = o;
        }
    }
}

extern "C" void kernel_launch(void* const* d_in, const int* in_sizes, int n_in,
                              void* d_out, int out_size)
{
    const float* A     = (const float*)d_in[0];
    const float* prior = (const float*)d_in[1];
    const float* W     = (const float*)d_in[2];
    const float* bias  = (const float*)d_in[3];
    const float* gamma = (const float*)d_in[4];
    const float* beta  = (const float*)d_in[5];
    const float* mmean = (const float*)d_in[6];
    const float* mvar  = (const float*)d_in[7];
    float* out = (float*)d_out;

    const int B = in_sizes[1] / FDIM;   // prior is [B, 512]
    const int grid = B / MT;
    const size_t smem = SMEM_FLOATS * sizeof(float);  // 77824 B

    cudaFuncSetAttribute(attn_fused_kernel,
                         cudaFuncAttributeMaxDynamicSharedMemorySize, (int)smem);
    attn_fused_kernel<<<grid, THREADS, smem>>>(A, prior, W, bias, gamma, beta,
                                               mmean, mvar, out);
}

// round 5
// speedup vs baseline: 1.3628x; 1.3628x over previous
#include <cuda_runtime.h>
#include <cuda_bf16.h>

#define FULL_MASK 0xffffffffu

constexpr int FDIM = 512;
constexpr int KDIM = 128;
constexpr int MT   = 64;          // rows per CTA
constexpr int BMAX = 65536;
constexpr float BN_EPS = 1e-3f;

// ---- scratch (device globals: allocation-free) ----
__device__ __nv_bfloat16 g_Ah[(size_t)BMAX * KDIM];
__device__ __nv_bfloat16 g_Al[(size_t)BMAX * KDIM];
__device__ __nv_bfloat16 g_Wh[(size_t)FDIM * KDIM];   // [f][k], k contiguous
__device__ __nv_bfloat16 g_Wl[(size_t)FDIM * KDIM];

// ---- smem layout (bytes) ----
// GEMM phase:   A_hi [0,16K)  A_lo [16K,32K)  W buf0 [32K,64K)  W buf1 [64K,96K)
//               (each W buf: hi 16K + lo 16K)
// epilogue:     zbuf [0, 64*516*4 = 132096) overlaps A/W
// always:       sS @133120 (2KB), sT @135168 (2KB)
constexpr int SM_A_HI = 0;
constexpr int SM_A_LO = 16384;
constexpr int SM_W0   = 32768;
constexpr int SM_W1   = 65536;
constexpr int ZSTRIDE = 516;              // floats
constexpr int SM_SS   = 133120;
constexpr int SM_TT   = 135168;
constexpr int SMEM_BYTES = 137216;

// ---- PTX helpers (base ISA only: no tcgen05/TMEM on this target) ----
__device__ __forceinline__ unsigned smem_u32(const void* p) {
    unsigned a;
    asm("{ .reg .u64 t; cvta.to.shared.u64 t, %1; cvt.u32.u64 %0, t; }" : "=r"(a) : "l"(p));
    return a;
}
__device__ __forceinline__ void cpa16(unsigned dst, const void* src) {
    asm volatile("cp.async.cg.shared.global [%0], [%1], 16;" :: "r"(dst), "l"(src));
}
__device__ __forceinline__ void cp_commit() {
    asm volatile("cp.async.commit_group;" ::: "memory");
}
__device__ __forceinline__ void cp_wait0() {
    asm volatile("cp.async.wait_group 0;" ::: "memory");
}
__device__ __forceinline__ void ldsm4(unsigned* r, unsigned addr) {
    asm volatile("ldmatrix.sync.aligned.m8n8.x4.shared.b16 {%0,%1,%2,%3}, [%4];"
        : "=r"(r[0]), "=r"(r[1]), "=r"(r[2]), "=r"(r[3]) : "r"(addr));
}
__device__ __forceinline__ void ldsm2(unsigned* r, unsigned addr) {
    asm volatile("ldmatrix.sync.aligned.m8n8.x2.shared.b16 {%0,%1}, [%2];"
        : "=r"(r[0]), "=r"(r[1]) : "r"(addr));
}
__device__ __forceinline__ void mma16816(float* d, const unsigned* a, const unsigned* b) {
    asm volatile(
        "mma.sync.aligned.m16n8k16.row.col.f32.bf16.bf16.f32 "
        "{%0,%1,%2,%3},{%4,%5,%6,%7},{%8,%9},{%0,%1,%2,%3};"
        : "+f"(d[0]), "+f"(d[1]), "+f"(d[2]), "+f"(d[3])
        : "r"(a[0]), "r"(a[1]), "r"(a[2]), "r"(a[3]), "r"(b[0]), "r"(b[1]));
}

// ================= conversion kernels =================
__global__ void conv_W_kernel(const float* __restrict__ W) {
    int idx = blockIdx.x * blockDim.x + threadIdx.x;   // 65536
    int k = idx >> 9;
    int f = idx & 511;
    float x = W[(size_t)k * FDIM + f];
    __nv_bfloat16 hi = __float2bfloat16(x);
    __nv_bfloat16 lo = __float2bfloat16(x - __bfloat162float(hi));
    g_Wh[(size_t)f * KDIM + k] = hi;
    g_Wl[(size_t)f * KDIM + k] = lo;
}

__global__ void conv_A_kernel(const float* __restrict__ A, int n2) {
    int i = blockIdx.x * blockDim.x + threadIdx.x;     // over float2's
    if (i >= n2) return;
    float2 x = ((const float2*)A)[i];
    __nv_bfloat16 h0 = __float2bfloat16(x.x);
    __nv_bfloat16 l0 = __float2bfloat16(x.x - __bfloat162float(h0));
    __nv_bfloat16 h1 = __float2bfloat16(x.y);
    __nv_bfloat16 l1 = __float2bfloat16(x.y - __bfloat162float(h1));
    __nv_bfloat162 hh; hh.x = h0; hh.y = h1;
    __nv_bfloat162 ll; ll.x = l0; ll.y = l1;
    ((__nv_bfloat162*)g_Ah)[i] = hh;
    ((__nv_bfloat162*)g_Al)[i] = ll;
}

// ================= main fused kernel =================
__global__ __launch_bounds__(512, 1)
void attn_mma_kernel(const float* __restrict__ prior,
                     const float* __restrict__ bias,
                     const float* __restrict__ gamma,
                     const float* __restrict__ beta,
                     const float* __restrict__ mmean,
                     const float* __restrict__ mvar,
                     float* __restrict__ out) {
    extern __shared__ char sm[];
    const unsigned smb = smem_u32(sm);
    float* sS = (float*)(sm + SM_SS);
    float* sT = (float*)(sm + SM_TT);

    const int tid  = threadIdx.x;
    const int wid  = tid >> 5;
    const int lane = tid & 31;
    const int wm   = wid >> 3;     // 0..1 : 32-row block
    const int wn   = wid & 7;      // 0..7 : 64-col slice
    const int rowbase = blockIdx.x * MT;

    // BN constants (bias folded): z = dot*s + t
    {
        float s = gamma[tid] * rsqrtf(mvar[tid] + BN_EPS);
        sS[tid] = s;
        sT[tid] = (bias[tid] - mmean[tid]) * s + beta[tid];
    }

    // ---- prologue: cp.async A tiles (hi+lo, swizzled) + W chunk 0 ----
#pragma unroll
    for (int p = 0; p < 4; p++) {
        int j   = p * 512 + tid;          // 2048 x uint4
        int sel = j >> 10;                // 0=hi 1=lo
        int rem = j & 1023;
        int r   = rem >> 4;
        int k8  = rem & 15;
        const __nv_bfloat16* src =
            (sel ? g_Al : g_Ah) + (size_t)(rowbase + r) * KDIM + k8 * 8;
        unsigned dst = smb + (sel ? SM_A_LO : SM_A_HI)
                     + r * 256 + ((k8 * 16) ^ ((r & 7) << 4));
        cpa16(dst, src);
    }
    {   // W chunk 0 -> buf0
#pragma unroll
        for (int p = 0; p < 4; p++) {
            int j   = p * 512 + tid;      // 2048 x uint4
            int sel = j >> 10;
            int rem = j & 1023;
            int n   = rem >> 1;
            int h   = rem & 1;
            const __nv_bfloat16* src =
                (sel ? g_Wl : g_Wh) + (size_t)n * KDIM + 0 * 16 + h * 8;
            unsigned dst = smb + SM_W0 + (sel ? 16384 : 0)
                         + n * 32 + ((h * 16) ^ (((n >> 2) & 1) << 4));
            cpa16(dst, src);
        }
    }
    cp_commit();

    float acc[2][8][4];
#pragma unroll
    for (int s = 0; s < 2; s++)
#pragma unroll
        for (int j = 0; j < 8; j++)
#pragma unroll
            for (int c = 0; c < 4; c++) acc[s][j][c] = 0.f;

    // ---- K loop: 8 chunks of 16, double-buffered W ----
#pragma unroll 1
    for (int kc = 0; kc < 8; kc++) {
        cp_wait0();
        __syncthreads();
        if (kc < 7) {
            const int base = ((kc + 1) & 1) ? SM_W1 : SM_W0;
#pragma unroll
            for (int p = 0; p < 4; p++) {
                int j   = p * 512 + tid;
                int sel = j >> 10;
                int rem = j & 1023;
                int n   = rem >> 1;
                int h   = rem & 1;
                const __nv_bfloat16* src =
                    (sel ? g_Wl : g_Wh) + (size_t)n * KDIM + (kc + 1) * 16 + h * 8;
                unsigned dst = smb + base + (sel ? 16384 : 0)
                             + n * 32 + ((h * 16) ^ (((n >> 2) & 1) << 4));
                cpa16(dst, src);
            }
            cp_commit();
        }
        const unsigned wb = smb + ((kc & 1) ? SM_W1 : SM_W0);

        // A fragments: [sub m16][pass hi/lo]
        unsigned afrag[2][2][4];
        {
            int rr = wm * 32 + (lane & 15);
            int kk = kc * 16 + ((lane >> 4) << 3);
            unsigned sw = (unsigned)((kk * 2) ^ ((rr & 7) << 4));
#pragma unroll
            for (int sub = 0; sub < 2; sub++) {
                unsigned rb = (unsigned)((rr + sub * 16) * 256) + sw;
                ldsm4(afrag[sub][0], smb + SM_A_HI + rb);
                ldsm4(afrag[sub][1], smb + SM_A_LO + rb);
            }
        }

        const int bn = wn * 64 + (lane & 7);
        const unsigned bko = (lane & 8) ? 16u : 0u;
#pragma unroll
        for (int j = 0; j < 8; j++) {
            int n = bn + j * 8;
            unsigned sw = (unsigned)(n * 32) + (bko ^ (((n >> 2) & 1) << 4));
            unsigned bh[2], bl[2];
            ldsm2(bh, wb + sw);
            ldsm2(bl, wb + 16384 + sw);
            mma16816(acc[0][j], afrag[0][0], bh);   // ah * wh
            mma16816(acc[1][j], afrag[1][0], bh);
            mma16816(acc[0][j], afrag[0][1], bh);   // al * wh
            mma16816(acc[1][j], afrag[1][1], bh);
            mma16816(acc[0][j], afrag[0][0], bl);   // ah * wl
            mma16816(acc[1][j], afrag[1][0], bl);
        }
    }
    __syncthreads();   // all MMA reads done; smem becomes zbuf

    // ---- write z = acc*s + t into zbuf (fragment layout scatter) ----
    float* zb = (float*)sm;
    {
        const int cbase = wn * 64 + (lane & 3) * 2;
        const int rbase = wm * 32 + (lane >> 2);
#pragma unroll
        for (int sub = 0; sub < 2; sub++) {
#pragma unroll
            for (int j = 0; j < 8; j++) {
                int c = cbase + j * 8;
                float2 sv = *(float2*)&sS[c];
                float2 tv = *(float2*)&sT[c];
                int r = rbase + sub * 16;
                float2 z0, z1;
                z0.x = fmaf(acc[sub][j][0], sv.x, tv.x);
                z0.y = fmaf(acc[sub][j][1], sv.y, tv.y);
                z1.x = fmaf(acc[sub][j][2], sv.x, tv.x);
                z1.y = fmaf(acc[sub][j][3], sv.y, tv.y);
                *(float2*)&zb[(size_t)r * ZSTRIDE + c] = z0;
                *(float2*)&zb[(size_t)(r + 8) * ZSTRIDE + c] = z1;
            }
        }
    }
    __syncthreads();

    // ---- sparsemax: warp owns 4 rows, 16 vals/lane ----
    float v[4][16];
    const int lr0 = wid * 4;
#pragma unroll
    for (int r = 0; r < 4; r++) {
        size_t g = (size_t)(rowbase + lr0 + r);
#pragma unroll
        for (int sg = 0; sg < 4; sg++) {
            float4 b  = *(float4*)&zb[(size_t)(lr0 + r) * ZSTRIDE + sg * 128 + lane * 4];
            float4 pr = *(const float4*)&prior[g * FDIM + sg * 128 + lane * 4];
            v[r][sg * 4 + 0] = b.x * pr.x;
            v[r][sg * 4 + 1] = b.y * pr.y;
            v[r][sg * 4 + 2] = b.z * pr.z;
            v[r][sg * 4 + 3] = b.w * pr.w;
        }
    }

    float mx[4];
#pragma unroll
    for (int r = 0; r < 4; r++) {
        float m = v[r][0];
#pragma unroll
        for (int i = 1; i < 16; i++) m = fmaxf(m, v[r][i]);
        mx[r] = m;
    }
#pragma unroll
    for (int off = 16; off; off >>= 1)
#pragma unroll
        for (int r = 0; r < 4; r++)
            mx[r] = fmaxf(mx[r], __shfl_xor_sync(FULL_MASK, mx[r], off));

    float lo[4], hi[4];
#pragma unroll
    for (int r = 0; r < 4; r++) { lo[r] = mx[r] - 1.0f; hi[r] = mx[r]; }
#pragma unroll 1
    for (int it = 0; it < 22; ++it) {
        float mid[4], s4[4];
#pragma unroll
        for (int r = 0; r < 4; r++) { mid[r] = 0.5f * (lo[r] + hi[r]); s4[r] = 0.f; }
#pragma unroll
        for (int r = 0; r < 4; r++)
#pragma unroll
            for (int i = 0; i < 16; i++)
                s4[r] += fmaxf(v[r][i] - mid[r], 0.f);
#pragma unroll
        for (int off = 16; off; off >>= 1)
#pragma unroll
            for (int r = 0; r < 4; r++)
                s4[r] += __shfl_xor_sync(FULL_MASK, s4[r], off);
#pragma unroll
        for (int r = 0; r < 4; r++) {
            if (s4[r] >= 1.0f) lo[r] = mid[r]; else hi[r] = mid[r];
        }
    }

#pragma unroll
    for (int r = 0; r < 4; r++) {
        const float tau = 0.5f * (lo[r] + hi[r]);
        size_t g = (size_t)(rowbase + lr0 + r);
#pragma unroll
        for (int sg = 0; sg < 4; sg++) {
            float4 o;
            o.x = fmaxf(v[r][sg * 4 + 0] - tau, 0.f);
            o.y = fmaxf(v[r][sg * 4 + 1] - tau, 0.f);
            o.z = fmaxf(v[r][sg * 4 + 2] - tau, 0.f);
            o.w = fmaxf(v[r][sg * 4 + 3] - tau, 0.f);
            *(float4*)&out[g * FDIM + sg * 128 + lane * 4] = o;
        }
    }
}

// ================= launch =================
extern "C" void kernel_launch(void* const* d_in, const int* in_sizes, int n_in,
                              void* d_out, int out_size) {
    const float* A     = (const float*)d_in[0];
    const float* prior = (const float*)d_in[1];
    const float* W     = (const float*)d_in[2];
    const float* bias  = (const float*)d_in[3];
    const float* gamma = (const float*)d_in[4];
    const float* beta  = (const float*)d_in[5];
    const float* mmean = (const float*)d_in[6];
    const float* mvar  = (const float*)d_in[7];
    float* out = (float*)d_out;

    const int B = in_sizes[1] / FDIM;          // prior is [B, 512]

    conv_W_kernel<<<128, 512>>>(W);
    const int n2 = B * (KDIM / 2);
    conv_A_kernel<<<(n2 + 511) / 512, 512>>>(A, n2);

    cudaFuncSetAttribute(attn_mma_kernel,
                         cudaFuncAttributeMaxDynamicSharedMemorySize, SMEM_BYTES);
    attn_mma_kernel<<<B / MT, 512, SMEM_BYTES>>>(prior, bias, gamma, beta,
                                                 mmean, mvar, out);
}